// round 3
// baseline (speedup 1.0000x reference)
#include <cuda_runtime.h>
#include <cuda_bf16.h>
#include <math_constants.h>

#define B_ROWS 4096
#define C_COLS 32000
#define C4     (C_COLS / 4)        // 8000 float4 per row
#define ROW_CHUNKS 64
#define ROWS_PER_CHUNK (B_ROWS / ROW_CHUNKS)   // 64
#define FINAL_BLOCKS 125           // 125 * 256 = 32000

// scratch (device globals — no allocation allowed)
__device__ float g_offset[B_ROWS];                    // per-row m + log(sum)
__device__ float g_partial[ROW_CHUNKS * C_COLS];      // 8 MB deterministic partials
__device__ int   g_counts[C_COLS];
__device__ float g_blocksum[FINAL_BLOCKS];
__device__ int   g_is32;                              // 1 = target is int32, 0 = int64

// ---------------------------------------------------------------------------
// online softmax update: exactly ONE expf per element
__device__ __forceinline__ void upd(float& m, float& s, float x) {
    if (x > m) { s = s * __expf(m - x) + 1.0f; m = x; }
    else       { s += __expf(x - m); }
}
__device__ __forceinline__ void comb(float& m, float& s, float m2, float s2) {
    float nm = fmaxf(m, m2);
    s = s * __expf(m - nm) + s2 * __expf(m2 - nm);
    m = nm;
}

// ---------------------------------------------------------------------------
__global__ void zero_counts() {
    int i = blockIdx.x * blockDim.x + threadIdx.x;
    if (i < C_COLS) g_counts[i] = 0;
}

// Detect target dtype. If the buffer holds int64 values in [0,32000), every
// odd 32-bit word (the high half) is zero. For int32 data those words are
// actual random targets, virtually surely nonzero somewhere. All inspected
// indices (<= 4095) fit within even the int32-sized buffer, so no OOB.
__global__ void detect_dtype(const int* __restrict__ w) {
    __shared__ int sh[256];
    int any = 0;
    for (int i = threadIdx.x; i < B_ROWS / 2; i += 256)
        any |= w[2 * i + 1];
    sh[threadIdx.x] = any;
    __syncthreads();
    for (int off = 128; off > 0; off >>= 1) {
        if (threadIdx.x < off) sh[threadIdx.x] |= sh[threadIdx.x + off];
        __syncthreads();
    }
    if (threadIdx.x == 0) g_is32 = (sh[0] != 0) ? 1 : 0;
}

// one block per row: online max/sum, store offset = m + log(s)
__global__ __launch_bounds__(256) void row_pass(const float* __restrict__ x) {
    const int b = blockIdx.x;
    const float4* row = reinterpret_cast<const float4*>(x + (size_t)b * C_COLS);

    // 4 independent (m,s) lanes to break the MUFU dependency chain
    float m0 = -CUDART_INF_F, m1 = -CUDART_INF_F, m2 = -CUDART_INF_F, m3 = -CUDART_INF_F;
    float s0 = 0.f, s1 = 0.f, s2 = 0.f, s3 = 0.f;

    for (int i = threadIdx.x; i < C4; i += 256) {
        float4 v = __ldg(&row[i]);
        upd(m0, s0, v.x);
        upd(m1, s1, v.y);
        upd(m2, s2, v.z);
        upd(m3, s3, v.w);
    }
    comb(m0, s0, m1, s1);
    comb(m2, s2, m3, s3);
    comb(m0, s0, m2, s2);

    __shared__ float sm[256];
    __shared__ float ss[256];
    sm[threadIdx.x] = m0;
    ss[threadIdx.x] = s0;
    __syncthreads();
    for (int off = 128; off > 0; off >>= 1) {
        if (threadIdx.x < off) {
            float mm = sm[threadIdx.x], sv = ss[threadIdx.x];
            comb(mm, sv, sm[threadIdx.x + off], ss[threadIdx.x + off]);
            sm[threadIdx.x] = mm;
            ss[threadIdx.x] = sv;
        }
        __syncthreads();
    }
    if (threadIdx.x == 0)
        g_offset[b] = sm[0] + __logf(ss[0]);
}

// grid (32, ROW_CHUNKS): thread owns 4 columns, sums exp(x-offset) over a
// 64-row chunk, writes a deterministic partial. No atomics.
__global__ __launch_bounds__(256) void col_pass(const float* __restrict__ x) {
    const int i4 = blockIdx.x * blockDim.x + threadIdx.x;
    if (i4 >= C4) return;
    const int r0 = blockIdx.y * ROWS_PER_CHUNK;
    const float4* xp = reinterpret_cast<const float4*>(x);

    float4 acc = make_float4(0.f, 0.f, 0.f, 0.f);
    #pragma unroll 4
    for (int r = r0; r < r0 + ROWS_PER_CHUNK; ++r) {
        const float off = g_offset[r];
        float4 v = __ldg(&xp[(size_t)r * C4 + i4]);
        acc.x += __expf(v.x - off);
        acc.y += __expf(v.y - off);
        acc.z += __expf(v.z - off);
        acc.w += __expf(v.w - off);
    }
    reinterpret_cast<float4*>(g_partial)[(size_t)blockIdx.y * C4 + i4] = acc;
}

// dtype-agnostic bincount; indices clamped as a hard safety net
__global__ void count_pass(const void* __restrict__ t) {
    int i = blockIdx.x * blockDim.x + threadIdx.x;
    if (i >= B_ROWS) return;
    int idx;
    if (g_is32) idx = ((const int*)t)[i];
    else        idx = (int)((const long long*)t)[i];
    idx = min(max(idx, 0), C_COLS - 1);
    atomicAdd(&g_counts[idx], 1);
}

// per-column: sum 64 partials, |colsum - count|, block-reduce
__global__ __launch_bounds__(256) void final_a() {
    const int c = blockIdx.x * blockDim.x + threadIdx.x;  // always < 32000
    float s = 0.f;
    #pragma unroll 8
    for (int k = 0; k < ROW_CHUNKS; ++k)
        s += g_partial[(size_t)k * C_COLS + c];
    float d = fabsf(s - (float)g_counts[c]);

    __shared__ float sh[256];
    sh[threadIdx.x] = d;
    __syncthreads();
    for (int off = 128; off > 0; off >>= 1) {
        if (threadIdx.x < off) sh[threadIdx.x] += sh[threadIdx.x + off];
        __syncthreads();
    }
    if (threadIdx.x == 0) g_blocksum[blockIdx.x] = sh[0];
}

__global__ void final_b(float* __restrict__ out) {
    __shared__ float sh[128];
    float s = 0.f;
    for (int i = threadIdx.x; i < FINAL_BLOCKS; i += 128) s += g_blocksum[i];
    sh[threadIdx.x] = s;
    __syncthreads();
    for (int off = 64; off > 0; off >>= 1) {
        if (threadIdx.x < off) sh[threadIdx.x] += sh[threadIdx.x + off];
        __syncthreads();
    }
    if (threadIdx.x == 0)
        out[0] = sh[0] * (1.0f / ((float)B_ROWS * (float)C_COLS));
}

// ---------------------------------------------------------------------------
extern "C" void kernel_launch(void* const* d_in, const int* in_sizes, int n_in,
                              void* d_out, int out_size) {
    // pick logits by element count (robust to input ordering)
    int li = 0, ti = 1;
    if (n_in >= 2 && in_sizes[1] > in_sizes[0]) { li = 1; ti = 0; }
    const float* logits = (const float*)d_in[li];
    const void*  target = d_in[ti];
    float* out = (float*)d_out;

    zero_counts<<<(C_COLS + 255) / 256, 256>>>();
    detect_dtype<<<1, 256>>>((const int*)target);
    row_pass<<<B_ROWS, 256>>>(logits);
    col_pass<<<dim3((C4 + 255) / 256, ROW_CHUNKS), 256>>>(logits);
    count_pass<<<(B_ROWS + 255) / 256, 256>>>(target);
    final_a<<<FINAL_BLOCKS, 256>>>();
    final_b<<<1, 128>>>(out);
}